// round 2
// baseline (speedup 1.0000x reference)
#include <cuda_runtime.h>
#include <cuda_bf16.h>
#include <math.h>

#define D_EMB 128
#define A_ATTR 16
#define IN_DIM 272
#define HID 128
#define NGROUPS 25000
#define MAX_E 500000

#define KT 16
#define TM 64

// ---------------- scratch (static device globals; no allocation) -------------
__device__ float g_logits[MAX_E];
__device__ float g_ex[MAX_E];
__device__ int   g_segmax[NGROUPS];
__device__ float g_segsum[NGROUPS];
__device__ int   g_is64;

// ---------------- helpers ----------------------------------------------------
__device__ __forceinline__ int order_key(float f) {
    int x = __float_as_int(f);
    return (x >= 0) ? x : (x ^ 0x7FFFFFFF);
}
__device__ __forceinline__ float order_dec(int k) {
    return (k >= 0) ? __int_as_float(k) : __int_as_float(k ^ 0x7FFFFFFF);
}
__device__ __forceinline__ int get_group(const void* gi, int e) {
    if (g_is64) return (int)((const long long*)gi)[e];
    return ((const int*)gi)[e];
}

// ---------------- kernels ----------------------------------------------------
__global__ void k_detect(const void* gi) {
    if (threadIdx.x == 0 && blockIdx.x == 0) {
        const long long* p = (const long long*)gi;
        int is64 = 1;
        for (int i = 0; i < 8; i++) {
            long long v = p[i];
            if (v < 0 || v >= (long long)NGROUPS) is64 = 0;
        }
        g_is64 = is64;
    }
}

__global__ void k_init() {
    int g = blockIdx.x * blockDim.x + threadIdx.x;
    if (g < NGROUPS) {
        g_segmax[g] = 0x80000000; // INT_MIN sentinel (below any order_key)
        g_segsum[g] = 0.0f;
    }
}

// C[64 edges, 128 hid] = F[64, 272] * W1[272, 128]; relu; dot W2 -> logit
__global__ __launch_bounds__(256) void k_mlp(
    const float* __restrict__ src, const float* __restrict__ dst,
    const float* __restrict__ attr,
    const float* __restrict__ W1, const float* __restrict__ b1,
    const float* __restrict__ W2, const float* __restrict__ b2,
    const void* __restrict__ gi, int E)
{
    __shared__ float As[KT][68];   // [k][m], padded: aligned float4 stores, broadcast reads
    __shared__ float Ws[KT][HID];  // [k][n]

    const int tid = threadIdx.x;
    const int c = tid & 31;   // n-group: n0 = 4c
    const int r = tid >> 5;   // m-group: m0 = 8r  (one warp == one r)
    const int m0 = r * 8;
    const int n0 = c * 4;
    const int ebase = blockIdx.x * TM;

    float acc[8][4];
#pragma unroll
    for (int i = 0; i < 8; i++)
#pragma unroll
        for (int j = 0; j < 4; j++) acc[i][j] = 0.0f;

    // A-loader indices: one float4 per thread per chunk
    const int lm = tid >> 2;          // 0..63 edge row
    const int lq = (tid & 3) * 4;     // k offset within chunk
    int le = ebase + lm; if (le >= E) le = E - 1;

    for (int kb = 0; kb < IN_DIM; kb += KT) {
        // ---- load feature tile (concat of src|dst|attr), transposed into As
        {
            int kg = kb + lq;
            const float* p;
            if (kg < D_EMB)            p = src  + (size_t)le * D_EMB  + kg;
            else if (kg < 2 * D_EMB)   p = dst  + (size_t)le * D_EMB  + (kg - D_EMB);
            else                       p = attr + (size_t)le * A_ATTR + (kg - 2 * D_EMB);
            float4 v = *(const float4*)p;
            As[lq + 0][lm] = v.x;
            As[lq + 1][lm] = v.y;
            As[lq + 2][lm] = v.z;
            As[lq + 3][lm] = v.w;
        }
        // ---- load W1 tile: 16x128 floats = 512 float4, 2 per thread
#pragma unroll
        for (int t = 0; t < 2; t++) {
            int idx = tid + t * 256;      // float4 index
            int k = idx >> 5;             // 32 float4 per row
            int n = (idx & 31) * 4;
            float4 w = *(const float4*)(W1 + (size_t)(kb + k) * HID + n);
            *(float4*)&Ws[k][n] = w;
        }
        __syncthreads();

#pragma unroll
        for (int k = 0; k < KT; k++) {
            float4 bf = *(const float4*)&Ws[k][n0];
            float4 a0 = *(const float4*)&As[k][m0];      // broadcast within warp
            float4 a1 = *(const float4*)&As[k][m0 + 4];
            float a[8] = {a0.x, a0.y, a0.z, a0.w, a1.x, a1.y, a1.z, a1.w};
            float b[4] = {bf.x, bf.y, bf.z, bf.w};
#pragma unroll
            for (int i = 0; i < 8; i++)
#pragma unroll
                for (int j = 0; j < 4; j++)
                    acc[i][j] = fmaf(a[i], b[j], acc[i][j]);
        }
        __syncthreads();
    }

    // ---- epilogue: bias, relu, W2 dot, warp reduce over 32 n-groups
    float bb[4], w2[4];
#pragma unroll
    for (int j = 0; j < 4; j++) {
        bb[j] = b1[n0 + j];
        w2[j] = W2[n0 + j];
    }
    float part[8];
#pragma unroll
    for (int i = 0; i < 8; i++) {
        float p = 0.0f;
#pragma unroll
        for (int j = 0; j < 4; j++) {
            float h = fmaxf(acc[i][j] + bb[j], 0.0f);
            p = fmaf(h, w2[j], p);
        }
        part[i] = p;
    }
#pragma unroll
    for (int off = 16; off > 0; off >>= 1)
#pragma unroll
        for (int i = 0; i < 8; i++)
            part[i] += __shfl_xor_sync(0xFFFFFFFFu, part[i], off);

    if (c == 0) {
        float b2v = b2[0];
#pragma unroll
        for (int i = 0; i < 8; i++) {
            int e = ebase + m0 + i;
            if (e < E) {
                float lg = part[i] + b2v;
                g_logits[e] = lg;
                int g = get_group(gi, e);
                atomicMax(&g_segmax[g], order_key(lg));
            }
        }
    }
}

__global__ void k_sum(const void* __restrict__ gi, int E) {
    int e = blockIdx.x * blockDim.x + threadIdx.x;
    if (e >= E) return;
    int g = get_group(gi, e);
    float m = order_dec(g_segmax[g]);
    float ex = expf(g_logits[e] - m);
    g_ex[e] = ex;
    atomicAdd(&g_segsum[g], ex);
}

__global__ void k_weights(const void* __restrict__ gi, float* __restrict__ out,
                          int E, int write_logits) {
    int e = blockIdx.x * blockDim.x + threadIdx.x;
    if (e >= E) return;
    int g = get_group(gi, e);
    out[e] = g_ex[e] / g_segsum[g];
    if (write_logits) out[E + e] = g_logits[e];
}

// ---------------- launch ------------------------------------------------------
extern "C" void kernel_launch(void* const* d_in, const int* in_sizes, int n_in,
                              void* d_out, int out_size) {
    const float* src  = (const float*)d_in[0];
    const float* dst  = (const float*)d_in[1];
    const float* attr = (const float*)d_in[2];
    const float* W1   = (const float*)d_in[3];
    const float* b1   = (const float*)d_in[4];
    const float* W2   = (const float*)d_in[5];
    const float* b2   = (const float*)d_in[6];
    const void*  gi   = d_in[7];
    float* out = (float*)d_out;

    const int E = in_sizes[2] / A_ATTR;  // edge_attr element count / 16
    const int write_logits = (out_size >= 2 * E) ? 1 : 0;

    k_detect<<<1, 32>>>(gi);
    k_init<<<(NGROUPS + 255) / 256, 256>>>();
    k_mlp<<<(E + TM - 1) / TM, 256>>>(src, dst, attr, W1, b1, W2, b2, gi, E);
    k_sum<<<(E + 255) / 256, 256>>>(gi, E);
    k_weights<<<(E + 255) / 256, 256>>>(gi, out, E, write_logits);
}

// round 5
// speedup vs baseline: 2.1337x; 2.1337x over previous
#include <cuda_runtime.h>
#include <cuda_fp16.h>
#include <math.h>
#include <stdint.h>

#define D_EMB 128
#define A_ATTR 16
#define IN_DIM 272
#define HID 128
#define NGROUPS 25000
#define MAX_E 500000

#define TILE_M 128
#define KCH 32
#define NCHUNK 9   // 4 src + 4 dst + 1 attr(16 valid)

// ---------------- scratch -----------------------------------------------------
__device__ float g_logits[MAX_E];
__device__ float g_ex[MAX_E];
__device__ int   g_segmax[NGROUPS];
__device__ float g_segsum[NGROUPS];
__device__ int   g_is64;
__device__ uint4 g_Bhi[NCHUNK * 512];   // 8KB per chunk: [k 0..31][n 0..127] fp16, swizzled
__device__ uint4 g_Blo[NCHUNK * 512];

// ---------------- helpers -----------------------------------------------------
__device__ __forceinline__ int order_key(float f) {
    int x = __float_as_int(f);
    return (x >= 0) ? x : (x ^ 0x7FFFFFFF);
}
__device__ __forceinline__ float order_dec(int k) {
    return (k >= 0) ? __int_as_float(k) : __int_as_float(k ^ 0x7FFFFFFF);
}
__device__ __forceinline__ int get_group(const void* gi, int e) {
    if (g_is64) return (int)((const long long*)gi)[e];
    return ((const int*)gi)[e];
}
__device__ __forceinline__ uint32_t smem_u32(const void* p) {
    uint32_t a;
    asm("{ .reg .u64 t; cvta.to.shared.u64 t, %1; cvt.u32.u64 %0, t; }" : "=r"(a) : "l"(p));
    return a;
}
__device__ __forceinline__ void ldmA(uint32_t* r, uint32_t addr) {
    asm volatile("ldmatrix.sync.aligned.m8n8.x4.shared.b16 {%0,%1,%2,%3}, [%4];"
                 : "=r"(r[0]), "=r"(r[1]), "=r"(r[2]), "=r"(r[3]) : "r"(addr));
}
__device__ __forceinline__ void ldmBT(uint32_t* r, uint32_t addr) {
    asm volatile("ldmatrix.sync.aligned.m8n8.x4.trans.shared.b16 {%0,%1,%2,%3}, [%4];"
                 : "=r"(r[0]), "=r"(r[1]), "=r"(r[2]), "=r"(r[3]) : "r"(addr));
}
__device__ __forceinline__ void mma16816(float* d, const uint32_t* a, const uint32_t* b) {
    asm volatile(
        "mma.sync.aligned.m16n8k16.row.col.f32.f16.f16.f32 "
        "{%0,%1,%2,%3}, {%4,%5,%6,%7}, {%8,%9}, {%0,%1,%2,%3};"
        : "+f"(d[0]), "+f"(d[1]), "+f"(d[2]), "+f"(d[3])
        : "r"(a[0]), "r"(a[1]), "r"(a[2]), "r"(a[3]), "r"(b[0]), "r"(b[1]));
}

// ---------------- small kernels ----------------------------------------------
__global__ void k_detect(const void* gi) {
    if (threadIdx.x == 0 && blockIdx.x == 0) {
        const long long* p = (const long long*)gi;
        int is64 = 1;
        for (int i = 0; i < 8; i++) {
            long long v = p[i];
            if (v < 0 || v >= (long long)NGROUPS) is64 = 0;
        }
        g_is64 = is64;
    }
}

__global__ void k_init() {
    int g = blockIdx.x * blockDim.x + threadIdx.x;
    if (g < NGROUPS) {
        g_segmax[g] = 0x80000000;
        g_segsum[g] = 0.0f;
    }
}

// Pre-swizzled fp16 hi/lo images of W1^T per 32-K chunk.
// image off = kk*256 + ((n>>3 ^ (kk&7))<<4) + (n&7)*2
__global__ void k_prep_w1(const float* __restrict__ W1) {
    int idx = blockIdx.x * blockDim.x + threadIdx.x;
    if (idx >= NCHUNK * KCH * HID) return;
    int k = idx >> 7;           // 0..287
    int n = idx & 127;
    float w = (k < IN_DIM) ? W1[(size_t)k * HID + n] : 0.0f;
    __half hi = __float2half_rn(w);
    __half lo = __float2half_rn(w - __half2float(hi));
    int chunk = k >> 5, kk = k & 31;
    uint32_t off = ((uint32_t)kk << 8)
                 + ((((uint32_t)(n >> 3)) ^ (uint32_t)(kk & 7)) << 4)
                 + ((uint32_t)(n & 7) << 1);
    ((__half*)g_Bhi)[chunk * 4096 + (off >> 1)] = hi;
    ((__half*)g_Blo)[chunk * 4096 + (off >> 1)] = lo;
}

// ---------------- main MLP kernel (HMMA fp16 hi/lo split, static smem) --------
__global__ void __launch_bounds__(256, 2) k_mlp_hmma(
    const float* __restrict__ src, const float* __restrict__ dst,
    const float* __restrict__ attr,
    const float* __restrict__ b1, const float* __restrict__ W2,
    const float* __restrict__ b2,
    const void* __restrict__ gi, int E)
{
    __shared__ __align__(256) char Ahi[8192];   // [m 0..127][k 0..31] fp16, 64B rows
    __shared__ __align__(256) char Alo[8192];
    __shared__ __align__(256) char Bhi[8192];   // [k 0..31][n 0..127] fp16, 256B rows
    __shared__ __align__(256) char Blo[8192];
    __shared__ float s_red[512];
    __shared__ float s_b1[128];
    __shared__ float s_w2[128];

    const uint32_t uAhi = smem_u32(Ahi), uAlo = smem_u32(Alo);
    const uint32_t uBhi = smem_u32(Bhi), uBlo = smem_u32(Blo);

    const int tid = threadIdx.x;
    const int lane = tid & 31;
    const int wid = tid >> 5;
    const int wm = wid >> 2;     // rows wm*64..+63
    const int wn = wid & 3;      // cols wn*32..+31
    const int ebase = blockIdx.x * TILE_M;

    if (tid < 128) { s_b1[tid] = b1[tid]; s_w2[tid] = W2[tid]; }

    float acc[4][4][4];
#pragma unroll
    for (int a = 0; a < 4; a++)
#pragma unroll
        for (int b = 0; b < 4; b++)
#pragma unroll
            for (int c = 0; c < 4; c++) acc[a][b][c] = 0.0f;

    const int sub = lane >> 3;
    const int li  = lane & 7;

    for (int kc = 0; kc < NCHUNK; kc++) {
        // ---- fill A: gather fp32, hi/lo fp16 split, swizzled store
        // rows of 32 floats = 8 float4 groups (attr chunk: 4 groups)
        const int gsh = (kc == 8) ? 2 : 3;
        const int ngrp = TILE_M << gsh;
        for (int it = tid; it < ngrp; it += 256) {
            int row = it >> gsh;
            int j = it & ((1 << gsh) - 1);
            int e = ebase + row; if (e >= E) e = E - 1;
            const float* p;
            if (kc < 4)      p = src  + (size_t)e * D_EMB  + kc * KCH + j * 4;
            else if (kc < 8) p = dst  + (size_t)e * D_EMB  + (kc - 4) * KCH + j * 4;
            else             p = attr + (size_t)e * A_ATTR + j * 4;
            float4 v = *(const float4*)p;
            __half h0 = __float2half_rn(v.x), h1 = __float2half_rn(v.y);
            __half h2 = __float2half_rn(v.z), h3 = __float2half_rn(v.w);
            __half l0 = __float2half_rn(v.x - __half2float(h0));
            __half l1 = __float2half_rn(v.y - __half2float(h1));
            __half l2 = __float2half_rn(v.z - __half2float(h2));
            __half l3 = __float2half_rn(v.w - __half2float(h3));
            __half2 hp0 = __halves2half2(h0, h1), hp1 = __halves2half2(h2, h3);
            __half2 lp0 = __halves2half2(l0, l1), lp1 = __halves2half2(l2, l3);
            uint32_t off = ((uint32_t)row << 6)
                         + ((((uint32_t)(j >> 1)) ^ (uint32_t)(row & 3)) << 4)
                         + ((uint32_t)(j & 1) << 3);
            *(uint2*)(Ahi + off) = make_uint2(*(uint32_t*)&hp0, *(uint32_t*)&hp1);
            *(uint2*)(Alo + off) = make_uint2(*(uint32_t*)&lp0, *(uint32_t*)&lp1);
        }
        // ---- copy pre-swizzled B images (8KB each)
        for (int it = tid; it < 512; it += 256) {
            ((uint4*)Bhi)[it] = g_Bhi[kc * 512 + it];
            ((uint4*)Blo)[it] = g_Blo[kc * 512 + it];
        }
        __syncthreads();

        const int nsteps = (kc == 8) ? 1 : 2;
        for (int ks = 0; ks < nsteps; ks++) {
            uint32_t bh[2][4], bl[2][4];
#pragma unroll
            for (int nb = 0; nb < 2; nb++) {
                int k = ks * 16 + (sub & 1) * 8 + li;
                int nch = ((wn * 32 + nb * 16) >> 3) + (sub >> 1);
                uint32_t boff = ((uint32_t)k << 8)
                              + (((uint32_t)nch ^ (uint32_t)(k & 7)) << 4);
                ldmBT(bh[nb], uBhi + boff);
                ldmBT(bl[nb], uBlo + boff);
            }
#pragma unroll
            for (int mi = 0; mi < 4; mi++) {
                int row = wm * 64 + mi * 16 + li + (sub & 1) * 8;
                int cidx = ks * 2 + (sub >> 1);   // 16B chunk within 64B row
                uint32_t aoff = ((uint32_t)row << 6)
                              + (((uint32_t)cidx ^ (uint32_t)(row & 3)) << 4);
                uint32_t ah[4], al[4];
                ldmA(ah, uAhi + aoff);
#pragma unroll
                for (int nb = 0; nb < 2; nb++) {
                    mma16816(acc[mi][nb * 2 + 0], ah, &bh[nb][0]);
                    mma16816(acc[mi][nb * 2 + 1], ah, &bh[nb][2]);
                    mma16816(acc[mi][nb * 2 + 0], ah, &bl[nb][0]);
                    mma16816(acc[mi][nb * 2 + 1], ah, &bl[nb][2]);
                }
                ldmA(al, uAlo + aoff);
#pragma unroll
                for (int nb = 0; nb < 2; nb++) {
                    mma16816(acc[mi][nb * 2 + 0], al, &bh[nb][0]);
                    mma16816(acc[mi][nb * 2 + 1], al, &bh[nb][2]);
                }
            }
        }
        __syncthreads();
    }

    // ---- epilogue: bias, relu, W2 partial dot, quad reduce, cross-warp combine
    const int q = lane >> 2, t = lane & 3;
#pragma unroll
    for (int mi = 0; mi < 4; mi++) {
        float plo = 0.0f, phi = 0.0f;
#pragma unroll
        for (int ni = 0; ni < 4; ni++) {
            int col = wn * 32 + ni * 8 + t * 2;
            float w0 = s_w2[col], w1v = s_w2[col + 1];
            float bb0 = s_b1[col], bb1 = s_b1[col + 1];
            plo = fmaf(fmaxf(acc[mi][ni][0] + bb0, 0.0f), w0, plo);
            plo = fmaf(fmaxf(acc[mi][ni][1] + bb1, 0.0f), w1v, plo);
            phi = fmaf(fmaxf(acc[mi][ni][2] + bb0, 0.0f), w0, phi);
            phi = fmaf(fmaxf(acc[mi][ni][3] + bb1, 0.0f), w1v, phi);
        }
        plo += __shfl_xor_sync(0xFFFFFFFFu, plo, 1);
        plo += __shfl_xor_sync(0xFFFFFFFFu, plo, 2);
        phi += __shfl_xor_sync(0xFFFFFFFFu, phi, 1);
        phi += __shfl_xor_sync(0xFFFFFFFFu, phi, 2);
        if (t == 0) {
            int r0 = wm * 64 + mi * 16 + q;
            s_red[wn * 128 + r0]     = plo;
            s_red[wn * 128 + r0 + 8] = phi;
        }
    }
    __syncthreads();

    if (tid < 128) {
        float s = s_red[tid] + s_red[128 + tid] + s_red[256 + tid] + s_red[384 + tid];
        int e = ebase + tid;
        if (e < E) {
            float lg = s + b2[0];
            g_logits[e] = lg;
            int g = get_group(gi, e);
            atomicMax(&g_segmax[g], order_key(lg));
        }
    }
}

__global__ void k_sum(const void* __restrict__ gi, int E) {
    int e = blockIdx.x * blockDim.x + threadIdx.x;
    if (e >= E) return;
    int g = get_group(gi, e);
    float m = order_dec(g_segmax[g]);
    float ex = expf(g_logits[e] - m);
    g_ex[e] = ex;
    atomicAdd(&g_segsum[g], ex);
}

__global__ void k_weights(const void* __restrict__ gi, float* __restrict__ out,
                          int E, int write_logits) {
    int e = blockIdx.x * blockDim.x + threadIdx.x;
    if (e >= E) return;
    int g = get_group(gi, e);
    out[e] = g_ex[e] / g_segsum[g];
    if (write_logits) out[E + e] = g_logits[e];
}

// ---------------- launch ------------------------------------------------------
extern "C" void kernel_launch(void* const* d_in, const int* in_sizes, int n_in,
                              void* d_out, int out_size) {
    const float* src  = (const float*)d_in[0];
    const float* dst  = (const float*)d_in[1];
    const float* attr = (const float*)d_in[2];
    const float* W1   = (const float*)d_in[3];
    const float* b1   = (const float*)d_in[4];
    const float* W2   = (const float*)d_in[5];
    const float* b2   = (const float*)d_in[6];
    const void*  gi   = d_in[7];
    float* out = (float*)d_out;

    const int E = in_sizes[2] / A_ATTR;
    const int write_logits = (out_size >= 2 * E) ? 1 : 0;

    k_detect<<<1, 32>>>(gi);
    k_init<<<(NGROUPS + 255) / 256, 256>>>();
    k_prep_w1<<<(NCHUNK * KCH * HID + 255) / 256, 256>>>(W1);
    k_mlp_hmma<<<(E + TILE_M - 1) / TILE_M, 256>>>(src, dst, attr, b1, W2, b2, gi, E);
    k_sum<<<(E + 255) / 256, 256>>>(gi, E);
    k_weights<<<(E + 255) / 256, 256>>>(gi, out, E, write_logits);
}

// round 8
// speedup vs baseline: 2.8834x; 1.3514x over previous
#include <cuda_runtime.h>
#include <cuda_fp16.h>
#include <math.h>
#include <stdint.h>

#define D_EMB 128
#define A_ATTR 16
#define IN_DIM 272
#define HID 128
#define NGROUPS 25000
#define MAX_E 500000

#define TILE_M 128
#define KCH 32
#define NCHUNK 9   // 4 src + 4 dst + 1 attr(16 valid)

// ---------------- scratch -----------------------------------------------------
__device__ float g_logits[MAX_E];
__device__ float g_ex[MAX_E];
__device__ int   g_segmax[NGROUPS];
__device__ float g_segsum[NGROUPS];
__device__ int   g_is64;
__device__ uint4 g_Bhi[NCHUNK * 512];   // 8KB/chunk: [k 0..31][n 0..127] fp16, swizzled
__device__ uint4 g_Blo[NCHUNK * 512];

// ---------------- helpers -----------------------------------------------------
__device__ __forceinline__ int order_key(float f) {
    int x = __float_as_int(f);
    return (x >= 0) ? x : (x ^ 0x7FFFFFFF);
}
__device__ __forceinline__ float order_dec(int k) {
    return (k >= 0) ? __int_as_float(k) : __int_as_float(k ^ 0x7FFFFFFF);
}
__device__ __forceinline__ int get_group(const void* gi, int e) {
    if (g_is64) return (int)((const long long*)gi)[e];
    return ((const int*)gi)[e];
}
__device__ __forceinline__ uint32_t smem_u32(const void* p) {
    uint32_t a;
    asm("{ .reg .u64 t; cvta.to.shared.u64 t, %1; cvt.u32.u64 %0, t; }" : "=r"(a) : "l"(p));
    return a;
}
__device__ __forceinline__ void cp_async16(uint32_t saddr, const void* gptr) {
    asm volatile("cp.async.cg.shared.global [%0], [%1], 16;"
                 :: "r"(saddr), "l"(gptr) : "memory");
}
__device__ __forceinline__ void cp_commit() {
    asm volatile("cp.async.commit_group;" ::: "memory");
}
__device__ __forceinline__ void ldmA(uint32_t* r, uint32_t addr) {
    asm volatile("ldmatrix.sync.aligned.m8n8.x4.shared.b16 {%0,%1,%2,%3}, [%4];"
                 : "=r"(r[0]), "=r"(r[1]), "=r"(r[2]), "=r"(r[3]) : "r"(addr));
}
__device__ __forceinline__ void ldmBT(uint32_t* r, uint32_t addr) {
    asm volatile("ldmatrix.sync.aligned.m8n8.x4.trans.shared.b16 {%0,%1,%2,%3}, [%4];"
                 : "=r"(r[0]), "=r"(r[1]), "=r"(r[2]), "=r"(r[3]) : "r"(addr));
}
__device__ __forceinline__ void mma16816(float* d, const uint32_t* a, const uint32_t* b) {
    asm volatile(
        "mma.sync.aligned.m16n8k16.row.col.f32.f16.f16.f32 "
        "{%0,%1,%2,%3}, {%4,%5,%6,%7}, {%8,%9}, {%0,%1,%2,%3};"
        : "+f"(d[0]), "+f"(d[1]), "+f"(d[2]), "+f"(d[3])
        : "r"(a[0]), "r"(a[1]), "r"(a[2]), "r"(a[3]), "r"(b[0]), "r"(b[1]));
}

// ---------------- small kernels ----------------------------------------------
__global__ void k_detect(const void* gi) {
    if (threadIdx.x == 0 && blockIdx.x == 0) {
        const long long* p = (const long long*)gi;
        int is64 = 1;
        for (int i = 0; i < 8; i++) {
            long long v = p[i];
            if (v < 0 || v >= (long long)NGROUPS) is64 = 0;
        }
        g_is64 = is64;
    }
}

__global__ void k_init() {
    int g = blockIdx.x * blockDim.x + threadIdx.x;
    if (g < NGROUPS) {
        g_segmax[g] = 0x80000000;
        g_segsum[g] = 0.0f;
    }
}

// Pre-swizzled fp16 hi/lo images of W1^T per 32-K chunk.
// image off = kk*256 + ((n>>3 ^ (kk&7))<<4) + (n&7)*2
__global__ void k_prep_w1(const float* __restrict__ W1) {
    int idx = blockIdx.x * blockDim.x + threadIdx.x;
    if (idx >= NCHUNK * KCH * HID) return;
    int k = idx >> 7;
    int n = idx & 127;
    float w = (k < IN_DIM) ? W1[(size_t)k * HID + n] : 0.0f;
    __half hi = __float2half_rn(w);
    __half lo = __float2half_rn(w - __half2float(hi));
    int chunk = k >> 5, kk = k & 31;
    uint32_t off = ((uint32_t)kk << 8)
                 + ((((uint32_t)(n >> 3)) ^ (uint32_t)(kk & 7)) << 4)
                 + ((uint32_t)(n & 7) << 1);
    ((__half*)g_Bhi)[chunk * 4096 + (off >> 1)] = hi;
    ((__half*)g_Blo)[chunk * 4096 + (off >> 1)] = lo;
}

// ---------------- main MLP kernel: 2-pass fp16 split, B double-buffered -------
__global__ void __launch_bounds__(256, 2) k_mlp_hmma(
    const float* __restrict__ src, const float* __restrict__ dst,
    const float* __restrict__ attr,
    const float* __restrict__ b1, const float* __restrict__ W2,
    const float* __restrict__ b2,
    const void* __restrict__ gi, int E)
{
    __shared__ __align__(256) char Ahi[8192];       // [m 0..127][k 0..31], 64B rows
    __shared__ __align__(256) char Bhi[2][8192];    // [k 0..31][n 0..127], 256B rows
    __shared__ __align__(256) char Blo[2][8192];
    __shared__ float s_red[512];
    __shared__ float s_b1[128];
    __shared__ float s_w2[128];

    const uint32_t uAhi = smem_u32(Ahi);
    const uint32_t uBhi = smem_u32(Bhi[0]);
    const uint32_t uBlo = smem_u32(Blo[0]);

    const int tid = threadIdx.x;
    const int lane = tid & 31;
    const int wid = tid >> 5;
    const int wm = wid >> 2;     // rows wm*64..+63
    const int wn = wid & 3;      // cols wn*32..+31
    const int ebase = blockIdx.x * TILE_M;

    if (tid < 128) { s_b1[tid] = b1[tid]; s_w2[tid] = W2[tid]; }

    float acc[4][4][4];
#pragma unroll
    for (int a = 0; a < 4; a++)
#pragma unroll
        for (int b = 0; b < 4; b++)
#pragma unroll
            for (int c = 0; c < 4; c++) acc[a][b][c] = 0.0f;

    const int sub = lane >> 3;
    const int li  = lane & 7;

    // ---- prefetch B(0)
    {
        uint32_t sh = uBhi + (uint32_t)tid * 16;
        uint32_t sl = uBlo + (uint32_t)tid * 16;
        cp_async16(sh, &g_Bhi[tid]);
        cp_async16(sh + 4096, &g_Bhi[256 + tid]);
        cp_async16(sl, &g_Blo[tid]);
        cp_async16(sl + 4096, &g_Blo[256 + tid]);
        cp_commit();
    }

    for (int kc = 0; kc < NCHUNK; kc++) {
        const uint32_t bb = (uint32_t)(kc & 1) * 8192;

        // ---- fill A: gather fp32, fp16 hi, swizzled store
        const int gsh = (kc == 8) ? 2 : 3;
        const int ngrp = TILE_M << gsh;
        for (int it = tid; it < ngrp; it += 256) {
            int row = it >> gsh;
            int j = it & ((1 << gsh) - 1);
            int e = ebase + row; if (e >= E) e = E - 1;
            const float* p;
            if (kc < 4)      p = src  + (size_t)e * D_EMB  + kc * KCH + j * 4;
            else if (kc < 8) p = dst  + (size_t)e * D_EMB  + (kc - 4) * KCH + j * 4;
            else             p = attr + (size_t)e * A_ATTR + j * 4;
            float4 v = *(const float4*)p;
            __half2 hp0 = __floats2half2_rn(v.x, v.y);
            __half2 hp1 = __floats2half2_rn(v.z, v.w);
            uint32_t off = ((uint32_t)row << 6)
                         + ((((uint32_t)(j >> 1)) ^ (uint32_t)(row & 3)) << 4)
                         + ((uint32_t)(j & 1) << 3);
            *(uint2*)(Ahi + off) = make_uint2(*(uint32_t*)&hp0, *(uint32_t*)&hp1);
        }
        // ---- prefetch B(kc+1) into other buffer
        if (kc + 1 < NCHUNK) {
            uint32_t ob = (uint32_t)((kc + 1) & 1) * 8192;
            uint32_t sh = uBhi + ob + (uint32_t)tid * 16;
            uint32_t sl = uBlo + ob + (uint32_t)tid * 16;
            const uint4* gh = &g_Bhi[(kc + 1) * 512];
            const uint4* gl = &g_Blo[(kc + 1) * 512];
            cp_async16(sh, gh + tid);
            cp_async16(sh + 4096, gh + 256 + tid);
            cp_async16(sl, gl + tid);
            cp_async16(sl + 4096, gl + 256 + tid);
            cp_commit();
            asm volatile("cp.async.wait_group 1;" ::: "memory");
        } else {
            asm volatile("cp.async.wait_group 0;" ::: "memory");
        }
        __syncthreads();

        const int nsteps = (kc == 8) ? 1 : 2;
        for (int ks = 0; ks < nsteps; ks++) {
            uint32_t bh[2][4], bl[2][4];
#pragma unroll
            for (int nb = 0; nb < 2; nb++) {
                int k = ks * 16 + (sub & 1) * 8 + li;
                int nch = ((wn * 32 + nb * 16) >> 3) + (sub >> 1);
                uint32_t boff = bb + ((uint32_t)k << 8)
                              + (((uint32_t)nch ^ (uint32_t)(k & 7)) << 4);
                ldmBT(bh[nb], uBhi + boff);
                ldmBT(bl[nb], uBlo + boff);
            }
#pragma unroll
            for (int mi = 0; mi < 4; mi++) {
                int row = wm * 64 + mi * 16 + li + (sub & 1) * 8;
                int cidx = ks * 2 + (sub >> 1);
                uint32_t aoff = ((uint32_t)row << 6)
                              + (((uint32_t)cidx ^ (uint32_t)(row & 3)) << 4);
                uint32_t ah[4];
                ldmA(ah, uAhi + aoff);
#pragma unroll
                for (int nb = 0; nb < 2; nb++) {
                    mma16816(acc[mi][nb * 2 + 0], ah, &bh[nb][0]);
                    mma16816(acc[mi][nb * 2 + 1], ah, &bh[nb][2]);
                    mma16816(acc[mi][nb * 2 + 0], ah, &bl[nb][0]);
                    mma16816(acc[mi][nb * 2 + 1], ah, &bl[nb][2]);
                }
            }
        }
        __syncthreads();
    }

    // ---- epilogue: bias, relu, W2 partial dot, quad reduce, cross-warp combine
    const int q = lane >> 2, t = lane & 3;
#pragma unroll
    for (int mi = 0; mi < 4; mi++) {
        float plo = 0.0f, phi = 0.0f;
#pragma unroll
        for (int ni = 0; ni < 4; ni++) {
            int col = wn * 32 + ni * 8 + t * 2;
            float w0 = s_w2[col], w1v = s_w2[col + 1];
            float bb0 = s_b1[col], bb1 = s_b1[col + 1];
            plo = fmaf(fmaxf(acc[mi][ni][0] + bb0, 0.0f), w0, plo);
            plo = fmaf(fmaxf(acc[mi][ni][1] + bb1, 0.0f), w1v, plo);
            phi = fmaf(fmaxf(acc[mi][ni][2] + bb0, 0.0f), w0, phi);
            phi = fmaf(fmaxf(acc[mi][ni][3] + bb1, 0.0f), w1v, phi);
        }
        plo += __shfl_xor_sync(0xFFFFFFFFu, plo, 1);
        plo += __shfl_xor_sync(0xFFFFFFFFu, plo, 2);
        phi += __shfl_xor_sync(0xFFFFFFFFu, phi, 1);
        phi += __shfl_xor_sync(0xFFFFFFFFu, phi, 2);
        if (t == 0) {
            int r0 = wm * 64 + mi * 16 + q;
            s_red[wn * 128 + r0]     = plo;
            s_red[wn * 128 + r0 + 8] = phi;
        }
    }
    __syncthreads();

    if (tid < 128) {
        float s = s_red[tid] + s_red[128 + tid] + s_red[256 + tid] + s_red[384 + tid];
        int e = ebase + tid;
        if (e < E) {
            float lg = s + b2[0];
            g_logits[e] = lg;
            int g = get_group(gi, e);
            atomicMax(&g_segmax[g], order_key(lg));
        }
    }
}

__global__ void k_sum(const void* __restrict__ gi, int E) {
    int e = blockIdx.x * blockDim.x + threadIdx.x;
    if (e >= E) return;
    int g = get_group(gi, e);
    float m = order_dec(g_segmax[g]);
    float ex = expf(g_logits[e] - m);
    g_ex[e] = ex;
    atomicAdd(&g_segsum[g], ex);
}

__global__ void k_weights(const void* __restrict__ gi, float* __restrict__ out,
                          int E, int write_logits) {
    int e = blockIdx.x * blockDim.x + threadIdx.x;
    if (e >= E) return;
    int g = get_group(gi, e);
    out[e] = g_ex[e] / g_segsum[g];
    if (write_logits) out[E + e] = g_logits[e];
}

// ---------------- launch ------------------------------------------------------
extern "C" void kernel_launch(void* const* d_in, const int* in_sizes, int n_in,
                              void* d_out, int out_size) {
    const float* src  = (const float*)d_in[0];
    const float* dst  = (const float*)d_in[1];
    const float* attr = (const float*)d_in[2];
    const float* W1   = (const float*)d_in[3];
    const float* b1   = (const float*)d_in[4];
    const float* W2   = (const float*)d_in[5];
    const float* b2   = (const float*)d_in[6];
    const void*  gi   = d_in[7];
    float* out = (float*)d_out;

    const int E = in_sizes[2] / A_ATTR;
    const int write_logits = (out_size >= 2 * E) ? 1 : 0;

    k_detect<<<1, 32>>>(gi);
    k_init<<<(NGROUPS + 255) / 256, 256>>>();
    k_prep_w1<<<(NCHUNK * KCH * HID + 255) / 256, 256>>>(W1);
    k_mlp_hmma<<<(E + TILE_M - 1) / TILE_M, 256>>>(src, dst, attr, b1, W2, b2, gi, E);
    k_sum<<<(E + 255) / 256, 256>>>(gi, E);
    k_weights<<<(E + 255) / 256, 256>>>(gi, out, E, write_logits);
}

// round 14
// speedup vs baseline: 4.5913x; 1.5923x over previous
#include <cuda_runtime.h>
#include <cuda_fp16.h>
#include <math.h>
#include <stdint.h>

#define D_EMB 128
#define A_ATTR 16
#define IN_DIM 272
#define HID 128
#define NGROUPS 25000
#define MAX_E 500000

#define TILE_M 128
#define KCH 32
#define NCHUNK 9   // 4 src + 4 dst + 1 attr(16 valid)

// ---------------- scratch -----------------------------------------------------
__device__ float g_logits[MAX_E];
__device__ float g_ex[MAX_E];
__device__ int   g_segmax[NGROUPS];
__device__ float g_segsum[NGROUPS];
__device__ int   g_is64;
__device__ uint4 g_Bh[NCHUNK * 512];   // 8KB/chunk: [k 0..31][n 0..127] fp16, swizzled

// ---------------- helpers -----------------------------------------------------
__device__ __forceinline__ int order_key(float f) {
    int x = __float_as_int(f);
    return (x >= 0) ? x : (x ^ 0x7FFFFFFF);
}
__device__ __forceinline__ float order_dec(int k) {
    return (k >= 0) ? __int_as_float(k) : __int_as_float(k ^ 0x7FFFFFFF);
}
__device__ __forceinline__ int get_group(const void* gi, int e) {
    if (g_is64) return (int)((const long long*)gi)[e];
    return ((const int*)gi)[e];
}
__device__ __forceinline__ uint32_t smem_u32(const void* p) {
    uint32_t a;
    asm("{ .reg .u64 t; cvta.to.shared.u64 t, %1; cvt.u32.u64 %0, t; }" : "=r"(a) : "l"(p));
    return a;
}
__device__ __forceinline__ void cp_async16(uint32_t saddr, const void* gptr) {
    asm volatile("cp.async.cg.shared.global [%0], [%1], 16;"
                 :: "r"(saddr), "l"(gptr) : "memory");
}
__device__ __forceinline__ void cp_commit() {
    asm volatile("cp.async.commit_group;" ::: "memory");
}
__device__ __forceinline__ void cp_wait_all() {
    asm volatile("cp.async.wait_group 0;" ::: "memory");
}
__device__ __forceinline__ void ldmA(uint32_t* r, uint32_t addr) {
    asm volatile("ldmatrix.sync.aligned.m8n8.x4.shared.b16 {%0,%1,%2,%3}, [%4];"
                 : "=r"(r[0]), "=r"(r[1]), "=r"(r[2]), "=r"(r[3]) : "r"(addr));
}
__device__ __forceinline__ void ldmBT(uint32_t* r, uint32_t addr) {
    asm volatile("ldmatrix.sync.aligned.m8n8.x4.trans.shared.b16 {%0,%1,%2,%3}, [%4];"
                 : "=r"(r[0]), "=r"(r[1]), "=r"(r[2]), "=r"(r[3]) : "r"(addr));
}
__device__ __forceinline__ void mma16816(float* d, const uint32_t* a, const uint32_t* b) {
    asm volatile(
        "mma.sync.aligned.m16n8k16.row.col.f32.f16.f16.f32 "
        "{%0,%1,%2,%3}, {%4,%5,%6,%7}, {%8,%9}, {%0,%1,%2,%3};"
        : "+f"(d[0]), "+f"(d[1]), "+f"(d[2]), "+f"(d[3])
        : "r"(a[0]), "r"(a[1]), "r"(a[2]), "r"(a[3]), "r"(b[0]), "r"(b[1]));
}

// ---------------- small kernels ----------------------------------------------
__global__ void k_detect(const void* gi) {
    if (threadIdx.x == 0 && blockIdx.x == 0) {
        const long long* p = (const long long*)gi;
        int is64 = 1;
        for (int i = 0; i < 8; i++) {
            long long v = p[i];
            if (v < 0 || v >= (long long)NGROUPS) is64 = 0;
        }
        g_is64 = is64;
    }
}

__global__ void k_init() {
    int g = blockIdx.x * blockDim.x + threadIdx.x;
    if (g < NGROUPS) {
        g_segmax[g] = 0x80000000;
        g_segsum[g] = 0.0f;
    }
}

// Pre-swizzled fp16 images of W1^T per 32-K chunk.
// off = kk*256 + ((n>>3 ^ (kk&7))<<4) + (n&7)*2
__global__ void k_prep_w1(const float* __restrict__ W1) {
    int idx = blockIdx.x * blockDim.x + threadIdx.x;
    if (idx >= NCHUNK * KCH * HID) return;
    int k = idx >> 7;
    int n = idx & 127;
    float w = (k < IN_DIM) ? W1[(size_t)k * HID + n] : 0.0f;
    int chunk = k >> 5, kk = k & 31;
    uint32_t off = ((uint32_t)kk << 8)
                 + ((((uint32_t)(n >> 3)) ^ (uint32_t)(kk & 7)) << 4)
                 + ((uint32_t)(n & 7) << 1);
    ((__half*)g_Bh)[chunk * 4096 + (off >> 1)] = __float2half_rn(w);
}

// ---------------- main MLP kernel: single-pass fp16, fully pipelined ----------
__global__ void __launch_bounds__(256, 2) k_mlp_hmma(
    const float* __restrict__ src, const float* __restrict__ dst,
    const float* __restrict__ attr,
    const float* __restrict__ b1, const float* __restrict__ W2,
    const float* __restrict__ b2,
    const void* __restrict__ gi, int E)
{
    __shared__ __align__(256) char AhiBuf[2][8192];  // [m 0..127][k 0..31], 64B rows
    __shared__ __align__(256) char BhiBuf[2][8192];  // [k 0..31][n 0..127], 256B rows

    // epilogue buffers alias AhiBuf[1] (dead after last MMA chunk, which uses buf 0)
    float* s_red = (float*)(AhiBuf[1]);          // 512 floats
    float* s_b1  = (float*)(AhiBuf[1] + 2048);   // 128 floats
    float* s_w2  = (float*)(AhiBuf[1] + 2560);   // 128 floats

    const uint32_t uAhi = smem_u32(AhiBuf[0]);
    const uint32_t uBhi = smem_u32(BhiBuf[0]);

    const int tid = threadIdx.x;
    const int lane = tid & 31;
    const int wid = tid >> 5;
    const int wm = wid >> 2;     // rows wm*64..+63
    const int wn = wid & 3;      // cols wn*32..+31
    const int ebase = blockIdx.x * TILE_M;
    const int sub = lane >> 3;
    const int li  = lane & 7;

    float acc[4][4][4];
#pragma unroll
    for (int a = 0; a < 4; a++)
#pragma unroll
        for (int b = 0; b < 4; b++)
#pragma unroll
            for (int c = 0; c < 4; c++) acc[a][b][c] = 0.0f;

    float4 pf[4];

    // ---- A gather for chunk kc into regs
    auto ldA = [&](int kc2) {
        const int n = (kc2 == 8) ? 2 : 4;
        const int gsh = (kc2 == 8) ? 2 : 3;
#pragma unroll
        for (int t = 0; t < 4; t++) {
            if (t >= n) break;
            int it = tid + t * 256;
            int row = it >> gsh;
            int j = it & ((1 << gsh) - 1);
            int e = ebase + row; if (e >= E) e = E - 1;
            const float* p;
            if (kc2 < 4)      p = src  + (size_t)e * D_EMB  + kc2 * KCH + j * 4;
            else if (kc2 < 8) p = dst  + (size_t)e * D_EMB  + (kc2 - 4) * KCH + j * 4;
            else              p = attr + (size_t)e * A_ATTR + j * 4;
            pf[t] = *(const float4*)p;
        }
    };
    // ---- convert regs -> fp16, swizzled store into Ahi buffer `b`
    auto stA = [&](int kc2, int b) {
        const int n = (kc2 == 8) ? 2 : 4;
        const int gsh = (kc2 == 8) ? 2 : 3;
        char* dsta = AhiBuf[b];
#pragma unroll
        for (int t = 0; t < 4; t++) {
            if (t >= n) break;
            int it = tid + t * 256;
            int row = it >> gsh;
            int j = it & ((1 << gsh) - 1);
            __half2 hp0 = __floats2half2_rn(pf[t].x, pf[t].y);
            __half2 hp1 = __floats2half2_rn(pf[t].z, pf[t].w);
            uint32_t off = ((uint32_t)row << 6)
                         + ((((uint32_t)(j >> 1)) ^ (uint32_t)(row & 3)) << 4)
                         + ((uint32_t)(j & 1) << 3);
            *(uint2*)(dsta + off) = make_uint2(*(uint32_t*)&hp0, *(uint32_t*)&hp1);
        }
    };
    // ---- cp.async B chunk kc into buffer
    auto pfB = [&](int kc2) {
        uint32_t sdst = uBhi + (uint32_t)(kc2 & 1) * 8192 + (uint32_t)tid * 16;
        const uint4* gsrc = &g_Bh[kc2 * 512];
        cp_async16(sdst, gsrc + tid);
        cp_async16(sdst + 4096, gsrc + 256 + tid);
        cp_commit();
    };

    // ---- prologue: A(0) direct, B(0) async
    pfB(0);
    ldA(0);
    stA(0, 0);

    for (int kc = 0; kc < NCHUNK; kc++) {
        const int buf = kc & 1;
        // 1. issue A(kc+1) loads (fly during MMA below)
        if (kc + 1 < NCHUNK) ldA(kc + 1);
        // 2. B(kc) must have landed; barrier also publishes Ahi stores of (kc)
        cp_wait_all();
        __syncthreads();
        // 3. B(kc+1) prefetch (write target Bhi[1-buf] safe: all reads of it done pre-barrier)
        if (kc + 1 < NCHUNK) pfB(kc + 1);

        // 4. MMA(kc)
        const uint32_t ab = uAhi + (uint32_t)buf * 8192;
        const uint32_t bb = uBhi + (uint32_t)buf * 8192;
        const int nsteps = (kc == 8) ? 1 : 2;
        for (int ks = 0; ks < nsteps; ks++) {
            uint32_t bh[2][4];
#pragma unroll
            for (int nb = 0; nb < 2; nb++) {
                int k = ks * 16 + (sub & 1) * 8 + li;
                int nch = ((wn * 32 + nb * 16) >> 3) + (sub >> 1);
                uint32_t boff = ((uint32_t)k << 8)
                              + (((uint32_t)nch ^ (uint32_t)(k & 7)) << 4);
                ldmBT(bh[nb], bb + boff);
            }
#pragma unroll
            for (int mi = 0; mi < 4; mi++) {
                int row = wm * 64 + mi * 16 + li + (sub & 1) * 8;
                int cidx = ks * 2 + (sub >> 1);
                uint32_t aoff = ((uint32_t)row << 6)
                              + (((uint32_t)cidx ^ (uint32_t)(row & 3)) << 4);
                uint32_t ah[4];
                ldmA(ah, ab + aoff);
#pragma unroll
                for (int nb = 0; nb < 2; nb++) {
                    mma16816(acc[mi][nb * 2 + 0], ah, &bh[nb][0]);
                    mma16816(acc[mi][nb * 2 + 1], ah, &bh[nb][2]);
                }
            }
        }
        // 5. convert + store A(kc+1) into other Ahi buffer
        if (kc + 1 < NCHUNK) stA(kc + 1, 1 - buf);
    }

    // ---- epilogue (aliases AhiBuf[1]; disjoint from last chunk's buf 0 reads)
    if (tid < 128) { s_b1[tid] = b1[tid]; s_w2[tid] = W2[tid]; }
    __syncthreads();

    const int q = lane >> 2, t = lane & 3;
#pragma unroll
    for (int mi = 0; mi < 4; mi++) {
        float plo = 0.0f, phi = 0.0f;
#pragma unroll
        for (int ni = 0; ni < 4; ni++) {
            int col = wn * 32 + ni * 8 + t * 2;
            float w0 = s_w2[col], w1v = s_w2[col + 1];
            float bb0 = s_b1[col], bb1 = s_b1[col + 1];
            plo = fmaf(fmaxf(acc[mi][ni][0] + bb0, 0.0f), w0, plo);
            plo = fmaf(fmaxf(acc[mi][ni][1] + bb1, 0.0f), w1v, plo);
            phi = fmaf(fmaxf(acc[mi][ni][2] + bb0, 0.0f), w0, phi);
            phi = fmaf(fmaxf(acc[mi][ni][3] + bb1, 0.0f), w1v, phi);
        }
        plo += __shfl_xor_sync(0xFFFFFFFFu, plo, 1);
        plo += __shfl_xor_sync(0xFFFFFFFFu, plo, 2);
        phi += __shfl_xor_sync(0xFFFFFFFFu, phi, 1);
        phi += __shfl_xor_sync(0xFFFFFFFFu, phi, 2);
        if (t == 0) {
            int r0 = wm * 64 + mi * 16 + q;
            s_red[wn * 128 + r0]     = plo;
            s_red[wn * 128 + r0 + 8] = phi;
        }
    }
    __syncthreads();

    if (tid < 128) {
        float s = s_red[tid] + s_red[128 + tid] + s_red[256 + tid] + s_red[384 + tid];
        int e = ebase + tid;
        if (e < E) {
            float lg = s + b2[0];
            g_logits[e] = lg;
            int g = get_group(gi, e);
            atomicMax(&g_segmax[g], order_key(lg));
        }
    }
}

__global__ void k_sum(const void* __restrict__ gi, int E) {
    int e = blockIdx.x * blockDim.x + threadIdx.x;
    if (e >= E) return;
    int g = get_group(gi, e);
    float m = order_dec(g_segmax[g]);
    float ex = expf(g_logits[e] - m);
    g_ex[e] = ex;
    atomicAdd(&g_segsum[g], ex);
}

__global__ void k_weights(const void* __restrict__ gi, float* __restrict__ out,
                          int E, int write_logits) {
    int e = blockIdx.x * blockDim.x + threadIdx.x;
    if (e >= E) return;
    int g = get_group(gi, e);
    out[e] = g_ex[e] / g_segsum[g];
    if (write_logits) out[E + e] = g_logits[e];
}

// ---------------- launch ------------------------------------------------------
extern "C" void kernel_launch(void* const* d_in, const int* in_sizes, int n_in,
                              void* d_out, int out_size) {
    const float* src  = (const float*)d_in[0];
    const float* dst  = (const float*)d_in[1];
    const float* attr = (const float*)d_in[2];
    const float* W1   = (const float*)d_in[3];
    const float* b1   = (const float*)d_in[4];
    const float* W2   = (const float*)d_in[5];
    const float* b2   = (const float*)d_in[6];
    const void*  gi   = d_in[7];
    float* out = (float*)d_out;

    const int E = in_sizes[2] / A_ATTR;
    const int write_logits = (out_size >= 2 * E) ? 1 : 0;

    k_detect<<<1, 32>>>(gi);
    k_init<<<(NGROUPS + 255) / 256, 256>>>();
    k_prep_w1<<<(NCHUNK * KCH * HID + 255) / 256, 256>>>(W1);
    k_mlp_hmma<<<(E + TILE_M - 1) / TILE_M, 256>>>(src, dst, attr, b1, W2, b2, gi, E);
    k_sum<<<(E + 255) / 256, 256>>>(gi, E);
    k_weights<<<(E + 255) / 256, 256>>>(gi, out, E, write_logits);
}